// round 14
// baseline (speedup 1.0000x reference)
#include <cuda_runtime.h>
#include <cuda_bf16.h>
#include <cstdint>

#define N_ROWS   4194304
#define N_DIM    64
#define N_IMG    1024

__device__ float g_sums[N_IMG * N_DIM];
__device__ int   g_counts[N_IMG];

#define BLOCKS   592              // exactly 4 per SM on 148 SMs
#define THREADS  192              // 6 warps
#define WARPS_PER_BLOCK (THREADS / 32)
#define N_WARPS  (BLOCKS * WARPS_PER_BLOCK)      // 3552

#define STAGE_ROWS  16
#define STAGE_FLOATS (STAGE_ROWS * N_DIM)        // 1024 floats
#define STAGE_BYTES (STAGE_FLOATS * 4)           // 4096
#define DEPTH 2
#define DYN_SMEM (WARPS_PER_BLOCK * DEPTH * STAGE_BYTES)   // 49152
#define TOTAL_STAGES (N_ROWS / STAGE_ROWS)       // 262144

// ---------------- PTX helpers ----------------
__device__ __forceinline__ unsigned smem_u32(const void* p) {
    return (unsigned)__cvta_generic_to_shared(p);
}
__device__ __forceinline__ void mbar_init(unsigned a) {
    asm volatile("mbarrier.init.shared.b64 [%0], 1;" :: "r"(a) : "memory");
}
__device__ __forceinline__ void mbar_expect_tx(unsigned a, unsigned bytes) {
    asm volatile("mbarrier.arrive.expect_tx.shared.b64 _, [%0], %1;"
                 :: "r"(a), "r"(bytes) : "memory");
}
__device__ __forceinline__ void bulk_load(unsigned dst, const void* src,
                                          unsigned bytes, unsigned mbar) {
    asm volatile(
        "cp.async.bulk.shared::cluster.global.mbarrier::complete_tx::bytes "
        "[%0], [%1], %2, [%3];"
        :: "r"(dst), "l"(src), "r"(bytes), "r"(mbar) : "memory");
}
__device__ __forceinline__ void mbar_wait(unsigned a, unsigned phase) {
    asm volatile(
        "{\n\t"
        ".reg .pred P;\n\t"
        "WLP_%=:\n\t"
        "mbarrier.try_wait.parity.acquire.cta.shared::cta.b64 P, [%0], %1, 0x989680;\n\t"
        "@P bra.uni WDN_%=;\n\t"
        "bra.uni WLP_%=;\n\t"
        "WDN_%=:\n\t"
        "}"
        :: "r"(a), "r"(phase) : "memory");
}

__global__ __launch_bounds__(THREADS, 4)
void main_kernel(const float* __restrict__ x,
                 const int* __restrict__ image_id,
                 float* __restrict__ out) {
    extern __shared__ __align__(16) float dyn_smem[];
    __shared__ __align__(8) unsigned long long stage_mbar[WARPS_PER_BLOCK][DEPTH];

    int wid  = threadIdx.x >> 5;
    int lane = threadIdx.x & 31;

    float* my_stages = dyn_smem + (size_t)wid * DEPTH * STAGE_FLOATS;

    if (lane < DEPTH) {
        mbar_init(smem_u32(&stage_mbar[wid][lane]));
    }
    __syncwarp();

    // ---- fused id copy: grid-stride over 1M int4
    {
        int tid = blockIdx.x * blockDim.x + threadIdx.x;
        const int4* src = reinterpret_cast<const int4*>(image_id);
        float4* dst = reinterpret_cast<float4*>(out + N_IMG * N_DIM);
        for (int i = tid; i < N_ROWS / 4; i += BLOCKS * THREADS) {
            int4 v = __ldcs(&src[i]);
            dst[i] = make_float4((float)v.x, (float)v.y, (float)v.z, (float)v.w);
        }
    }

    int gwarp = blockIdx.x * WARPS_PER_BLOCK + wid;
    int half  = lane >> 4;        // 0: even row of pair, 1: odd row
    int sub   = lane & 15;        // float4 slot (4 dims) within a row

    // contiguous stage range per warp (16-row granularity): ~73-74 stages
    int s_begin = (int)(((long long)gwarp       * TOTAL_STAGES) / N_WARPS);
    int s_end   = (int)(((long long)(gwarp + 1) * TOTAL_STAGES) / N_WARPS);
    int r0      = s_begin * STAGE_ROWS;
    int nstages = s_end - s_begin;

    unsigned mb[DEPTH];
    unsigned db[DEPTH];
    int phase[DEPTH];
    #pragma unroll
    for (int s = 0; s < DEPTH; ++s) {
        mb[s] = smem_u32(&stage_mbar[wid][s]);
        db[s] = smem_u32(my_stages + s * STAGE_FLOATS);
        phase[s] = 0;
    }

    // prologue: fill all DEPTH buffers
    if (lane == 0) {
        #pragma unroll
        for (int s = 0; s < DEPTH; ++s) {
            if (s < nstages) {
                mbar_expect_tx(mb[s], STAGE_BYTES);
                bulk_load(db[s], x + (size_t)(r0 + s * STAGE_ROWS) * N_DIM,
                          STAGE_BYTES, mb[s]);
            }
        }
    }

    float4 acc = make_float4(0.f, 0.f, 0.f, 0.f);
    int cur = -1;
    int runlen = 0;

    #define FLUSH()                                                          \
        do {                                                                 \
            if (runlen > 0) {                                                \
                float4 t = acc;                                              \
                t.x += __shfl_down_sync(0xffffffff, t.x, 16);                \
                t.y += __shfl_down_sync(0xffffffff, t.y, 16);                \
                t.z += __shfl_down_sync(0xffffffff, t.z, 16);                \
                t.w += __shfl_down_sync(0xffffffff, t.w, 16);                \
                if (half == 0) {                                             \
                    float* s_ = &g_sums[cur * N_DIM + sub * 4];              \
                    atomicAdd(s_ + 0, t.x);                                  \
                    atomicAdd(s_ + 1, t.y);                                  \
                    atomicAdd(s_ + 2, t.z);                                  \
                    atomicAdd(s_ + 3, t.w);                                  \
                }                                                            \
                if (lane == 0) atomicAdd(&g_counts[cur], runlen);            \
                acc = make_float4(0.f, 0.f, 0.f, 0.f);                       \
                runlen = 0;                                                  \
            }                                                                \
        } while (0)

    int buf = 0;
    for (int s = 0; s < nstages; ++s) {
        mbar_wait(mb[buf], phase[buf]);
        phase[buf] ^= 1;

        int sr = r0 + s * STAGE_ROWS;
        int ida = __ldg(&image_id[sr]);
        int idb = __ldg(&image_id[sr + STAGE_ROWS - 1]);
        const float* sbase = my_stages + buf * STAGE_FLOATS;

        if (ida == idb) {
            // fast stage: uniform segment across its 16 rows
            if (ida != cur) { FLUSH(); cur = ida; }
            const float4* sp = reinterpret_cast<const float4*>(sbase);
            #pragma unroll
            for (int j = 0; j < STAGE_ROWS / 2; ++j) {
                float4 v = sp[(2 * j + half) * (N_DIM / 4) + sub];
                acc.x += v.x; acc.y += v.y; acc.z += v.z; acc.w += v.w;
            }
            runlen += STAGE_ROWS;
        } else {
            // slow stage: boundary inside; per-row float2 from smem
            FLUSH();
            const float2* sp2 = reinterpret_cast<const float2*>(sbase);
            float2 sacc = make_float2(0.f, 0.f);
            int scur = ida;
            int srun = 0;
            #pragma unroll
            for (int r = 0; r < STAGE_ROWS; ++r) {
                int id = __ldg(&image_id[sr + r]);
                if (id != scur) {
                    atomicAdd(&g_sums[scur * N_DIM + lane * 2 + 0], sacc.x);
                    atomicAdd(&g_sums[scur * N_DIM + lane * 2 + 1], sacc.y);
                    if (lane == 0) atomicAdd(&g_counts[scur], srun);
                    sacc = make_float2(0.f, 0.f);
                    scur = id;
                    srun = 0;
                }
                float2 v = sp2[r * (N_DIM / 2) + lane];
                sacc.x += v.x;
                sacc.y += v.y;
                ++srun;
            }
            atomicAdd(&g_sums[scur * N_DIM + lane * 2 + 0], sacc.x);
            atomicAdd(&g_sums[scur * N_DIM + lane * 2 + 1], sacc.y);
            if (lane == 0) atomicAdd(&g_counts[scur], srun);
            cur = -1;
        }

        // refill this buffer with stage s+DEPTH
        int ns = s + DEPTH;
        if (ns < nstages && lane == 0) {
            mbar_expect_tx(mb[buf], STAGE_BYTES);
            bulk_load(db[buf], x + (size_t)(r0 + ns * STAGE_ROWS) * N_DIM,
                      STAGE_BYTES, mb[buf]);
        }
        buf = (buf + 1 == DEPTH) ? 0 : buf + 1;
    }
    FLUSH();
    #undef FLUSH
}

// ---------------------------------------------------------------------------
// merged finalize: block b owns images [4b, 4b+4). All reads of g_counts[img]
// (both the 64 averaged-row readers and the tail writer) happen inside block
// b, so an in-block __syncthreads() makes re-zeroing race-free.
// grid = 256 blocks x 256 threads.
// ---------------------------------------------------------------------------
__global__ void finalize_kernel(float* __restrict__ out) {
    int gid = blockIdx.x * blockDim.x + threadIdx.x;     // 0 .. 65535
    int img = gid >> 6;                                  // 4b + (t>>6)
    int c = g_counts[img];
    float denom = (float)(c > 0 ? c : 1);
    out[gid] = g_sums[gid] / denom;
    if (threadIdx.x < 4) {
        int my_img = blockIdx.x * 4 + threadIdx.x;
        out[N_IMG * N_DIM + N_ROWS + my_img] = (float)g_counts[my_img];
    }
    __syncthreads();
    g_sums[gid] = 0.0f;
    if (threadIdx.x < 4) {
        g_counts[blockIdx.x * 4 + threadIdx.x] = 0;
    }
}

// ---------------------------------------------------------------------------
extern "C" void kernel_launch(void* const* d_in, const int* in_sizes, int n_in,
                              void* d_out, int out_size) {
    const float* x = nullptr;
    const int* image_id = nullptr;
    for (int i = 0; i < n_in; ++i) {
        if (in_sizes[i] == N_ROWS * N_DIM) x = (const float*)d_in[i];
        else if (in_sizes[i] == N_ROWS)    image_id = (const int*)d_in[i];
    }
    float* out = (float*)d_out;

    static bool attr_set = false;
    if (!attr_set) {
        cudaFuncSetAttribute(main_kernel,
                             cudaFuncAttributeMaxDynamicSharedMemorySize,
                             DYN_SMEM);
        attr_set = true;
    }

    main_kernel<<<BLOCKS, THREADS, DYN_SMEM>>>(x, image_id, out);
    finalize_kernel<<<256, 256>>>(out);
}

// round 15
// speedup vs baseline: 1.0751x; 1.0751x over previous
#include <cuda_runtime.h>
#include <cuda_bf16.h>
#include <cstdint>

#define N_ROWS   4194304
#define N_DIM    64
#define N_IMG    1024

__device__ float g_sums[N_IMG * N_DIM];
__device__ int   g_counts[N_IMG];

#define BLOCKS   592              // exactly 4 per SM on 148 SMs
#define THREADS  256
#define WARPS_PER_BLOCK (THREADS / 32)
#define N_WARPS  (BLOCKS * WARPS_PER_BLOCK)      // 4736

#define STAGE_ROWS  8
#define STAGE_FLOATS (STAGE_ROWS * N_DIM)        // 512 floats
#define STAGE_BYTES (STAGE_FLOATS * 4)           // 2048
#define DEPTH 3
#define DYN_SMEM (WARPS_PER_BLOCK * DEPTH * STAGE_BYTES)   // 49152
#define TOTAL_STAGES (N_ROWS / STAGE_ROWS)       // 524288

// ---------------- PTX helpers ----------------
__device__ __forceinline__ unsigned smem_u32(const void* p) {
    return (unsigned)__cvta_generic_to_shared(p);
}
__device__ __forceinline__ void mbar_init(unsigned a) {
    asm volatile("mbarrier.init.shared.b64 [%0], 1;" :: "r"(a) : "memory");
}
__device__ __forceinline__ void mbar_expect_tx(unsigned a, unsigned bytes) {
    asm volatile("mbarrier.arrive.expect_tx.shared.b64 _, [%0], %1;"
                 :: "r"(a), "r"(bytes) : "memory");
}
__device__ __forceinline__ void bulk_load(unsigned dst, const void* src,
                                          unsigned bytes, unsigned mbar) {
    asm volatile(
        "cp.async.bulk.shared::cluster.global.mbarrier::complete_tx::bytes "
        "[%0], [%1], %2, [%3];"
        :: "r"(dst), "l"(src), "r"(bytes), "r"(mbar) : "memory");
}
__device__ __forceinline__ void mbar_wait(unsigned a, unsigned phase) {
    asm volatile(
        "{\n\t"
        ".reg .pred P;\n\t"
        "WLP_%=:\n\t"
        "mbarrier.try_wait.parity.acquire.cta.shared::cta.b64 P, [%0], %1, 0x989680;\n\t"
        "@P bra.uni WDN_%=;\n\t"
        "bra.uni WLP_%=;\n\t"
        "WDN_%=:\n\t"
        "}"
        :: "r"(a), "r"(phase) : "memory");
}

__global__ __launch_bounds__(THREADS, 4)
void main_kernel(const float* __restrict__ x,
                 const int* __restrict__ image_id,
                 float* __restrict__ out) {
    extern __shared__ __align__(16) float dyn_smem[];
    __shared__ __align__(8) unsigned long long stage_mbar[WARPS_PER_BLOCK][DEPTH];

    int wid  = threadIdx.x >> 5;
    int lane = threadIdx.x & 31;

    float* my_stages = dyn_smem + (size_t)wid * DEPTH * STAGE_FLOATS;

    if (lane < DEPTH) {
        mbar_init(smem_u32(&stage_mbar[wid][lane]));
    }
    __syncwarp();

    // ---- fused id copy: grid-stride over 1M int4
    {
        int tid = blockIdx.x * blockDim.x + threadIdx.x;
        const int4* src = reinterpret_cast<const int4*>(image_id);
        float4* dst = reinterpret_cast<float4*>(out + N_IMG * N_DIM);
        for (int i = tid; i < N_ROWS / 4; i += BLOCKS * THREADS) {
            int4 v = __ldcs(&src[i]);
            dst[i] = make_float4((float)v.x, (float)v.y, (float)v.z, (float)v.w);
        }
    }

    int gwarp = blockIdx.x * WARPS_PER_BLOCK + wid;
    int half  = lane >> 4;        // 0: even row of pair, 1: odd row
    int sub   = lane & 15;        // float4 slot (4 dims) within a row

    // contiguous stage range per warp, 8-row granularity: 110 or 111 stages
    int s_begin = (int)(((long long)gwarp       * TOTAL_STAGES) / N_WARPS);
    int s_end   = (int)(((long long)(gwarp + 1) * TOTAL_STAGES) / N_WARPS);
    int r0      = s_begin * STAGE_ROWS;
    int nstages = s_end - s_begin;

    unsigned mb[DEPTH];
    unsigned db[DEPTH];
    int phase[DEPTH];
    #pragma unroll
    for (int s = 0; s < DEPTH; ++s) {
        mb[s] = smem_u32(&stage_mbar[wid][s]);
        db[s] = smem_u32(my_stages + s * STAGE_FLOATS);
        phase[s] = 0;
    }

    // prologue: fill all DEPTH buffers
    if (lane == 0) {
        #pragma unroll
        for (int s = 0; s < DEPTH; ++s) {
            if (s < nstages) {
                mbar_expect_tx(mb[s], STAGE_BYTES);
                bulk_load(db[s], x + (size_t)(r0 + s * STAGE_ROWS) * N_DIM,
                          STAGE_BYTES, mb[s]);
            }
        }
    }

    float4 acc = make_float4(0.f, 0.f, 0.f, 0.f);
    int cur = -1;
    int runlen = 0;

    #define FLUSH()                                                          \
        do {                                                                 \
            if (runlen > 0) {                                                \
                float4 t = acc;                                              \
                t.x += __shfl_down_sync(0xffffffff, t.x, 16);                \
                t.y += __shfl_down_sync(0xffffffff, t.y, 16);                \
                t.z += __shfl_down_sync(0xffffffff, t.z, 16);                \
                t.w += __shfl_down_sync(0xffffffff, t.w, 16);                \
                if (half == 0) {                                             \
                    float* s_ = &g_sums[cur * N_DIM + sub * 4];              \
                    atomicAdd(s_ + 0, t.x);                                  \
                    atomicAdd(s_ + 1, t.y);                                  \
                    atomicAdd(s_ + 2, t.z);                                  \
                    atomicAdd(s_ + 3, t.w);                                  \
                }                                                            \
                if (lane == 0) atomicAdd(&g_counts[cur], runlen);            \
                acc = make_float4(0.f, 0.f, 0.f, 0.f);                       \
                runlen = 0;                                                  \
            }                                                                \
        } while (0)

    int buf = 0;
    for (int s = 0; s < nstages; ++s) {
        mbar_wait(mb[buf], phase[buf]);
        phase[buf] ^= 1;

        int sr = r0 + s * STAGE_ROWS;
        int ida = __ldg(&image_id[sr]);
        int idb = __ldg(&image_id[sr + STAGE_ROWS - 1]);
        const float* sbase = my_stages + buf * STAGE_FLOATS;

        if (ida == idb) {
            // fast stage: uniform segment across its 8 rows
            if (ida != cur) { FLUSH(); cur = ida; }
            const float4* sp = reinterpret_cast<const float4*>(sbase);
            #pragma unroll
            for (int j = 0; j < STAGE_ROWS / 2; ++j) {
                float4 v = sp[(2 * j + half) * (N_DIM / 4) + sub];
                acc.x += v.x; acc.y += v.y; acc.z += v.z; acc.w += v.w;
            }
            runlen += STAGE_ROWS;
        } else {
            // slow stage: boundary inside; per-row float2 from smem
            FLUSH();
            const float2* sp2 = reinterpret_cast<const float2*>(sbase);
            float2 sacc = make_float2(0.f, 0.f);
            int scur = ida;
            int srun = 0;
            #pragma unroll
            for (int r = 0; r < STAGE_ROWS; ++r) {
                int id = __ldg(&image_id[sr + r]);
                if (id != scur) {
                    atomicAdd(&g_sums[scur * N_DIM + lane * 2 + 0], sacc.x);
                    atomicAdd(&g_sums[scur * N_DIM + lane * 2 + 1], sacc.y);
                    if (lane == 0) atomicAdd(&g_counts[scur], srun);
                    sacc = make_float2(0.f, 0.f);
                    scur = id;
                    srun = 0;
                }
                float2 v = sp2[r * (N_DIM / 2) + lane];
                sacc.x += v.x;
                sacc.y += v.y;
                ++srun;
            }
            atomicAdd(&g_sums[scur * N_DIM + lane * 2 + 0], sacc.x);
            atomicAdd(&g_sums[scur * N_DIM + lane * 2 + 1], sacc.y);
            if (lane == 0) atomicAdd(&g_counts[scur], srun);
            cur = -1;
        }

        // refill this buffer with stage s+DEPTH
        int ns = s + DEPTH;
        if (ns < nstages && lane == 0) {
            mbar_expect_tx(mb[buf], STAGE_BYTES);
            bulk_load(db[buf], x + (size_t)(r0 + ns * STAGE_ROWS) * N_DIM,
                      STAGE_BYTES, mb[buf]);
        }
        buf = (buf + 1 == DEPTH) ? 0 : buf + 1;
    }
    FLUSH();
    #undef FLUSH
}

// ---------------------------------------------------------------------------
// merged finalize: block b owns images [4b, 4b+4). All reads of g_counts[img]
// (both the 64 averaged-row readers and the tail writer) happen inside block
// b, so an in-block __syncthreads() makes re-zeroing race-free.
// grid = 256 blocks x 256 threads.
// ---------------------------------------------------------------------------
__global__ void finalize_kernel(float* __restrict__ out) {
    int gid = blockIdx.x * blockDim.x + threadIdx.x;     // 0 .. 65535
    int img = gid >> 6;                                  // 4b + (t>>6)
    int c = g_counts[img];
    float denom = (float)(c > 0 ? c : 1);
    out[gid] = g_sums[gid] / denom;
    if (threadIdx.x < 4) {
        int my_img = blockIdx.x * 4 + threadIdx.x;
        out[N_IMG * N_DIM + N_ROWS + my_img] = (float)g_counts[my_img];
    }
    __syncthreads();
    g_sums[gid] = 0.0f;
    if (threadIdx.x < 4) {
        g_counts[blockIdx.x * 4 + threadIdx.x] = 0;
    }
}

// ---------------------------------------------------------------------------
extern "C" void kernel_launch(void* const* d_in, const int* in_sizes, int n_in,
                              void* d_out, int out_size) {
    const float* x = nullptr;
    const int* image_id = nullptr;
    for (int i = 0; i < n_in; ++i) {
        if (in_sizes[i] == N_ROWS * N_DIM) x = (const float*)d_in[i];
        else if (in_sizes[i] == N_ROWS)    image_id = (const int*)d_in[i];
    }
    float* out = (float*)d_out;

    static bool attr_set = false;
    if (!attr_set) {
        cudaFuncSetAttribute(main_kernel,
                             cudaFuncAttributeMaxDynamicSharedMemorySize,
                             DYN_SMEM);
        attr_set = true;
    }

    main_kernel<<<BLOCKS, THREADS, DYN_SMEM>>>(x, image_id, out);
    finalize_kernel<<<256, 256>>>(out);
}